// round 1
// baseline (speedup 1.0000x reference)
#include <cuda_runtime.h>
#include <cstdint>

// IndRNN: proj = x @ W + b  (GEMM, written to d_out as scratch/final buffer),
// then per-(b,u) sequential scan: h_t = relu(proj_t + h_{t-1} * clip(u,0,1)).
//
// Kernel 1: fp32 SIMT tiled GEMM (BM=64, BN=64, BK=16, 4x4 microtile, 256 thr).
// Kernel 2: scan with 8-deep timestep prefetch to manufacture MLP.

#define BM 64
#define BN 64
#define BK 16
#define TM 4
#define TN 4

__global__ __launch_bounds__(256) void indrnn_gemm_bias(
    const float* __restrict__ A,   // X [M, K] row-major
    const float* __restrict__ Bw,  // W [K, N] row-major
    const float* __restrict__ bias,// [N]
    float* __restrict__ C,         // [M, N]
    int M, int N, int K)
{
    __shared__ float As[BK][BM];   // transposed A tile
    __shared__ float Bs[BK][BN];

    const int tid = threadIdx.x;
    const int m0 = blockIdx.y * BM;
    const int n0 = blockIdx.x * BN;

    // A tile load: 64 rows x 16 cols, one float4 per thread
    const int a_row = tid >> 2;          // 0..63
    const int a_col = (tid & 3) * 4;     // 0,4,8,12
    // B tile load: 16 rows x 64 cols, one float4 per thread
    const int b_row = tid >> 4;          // 0..15
    const int b_col = (tid & 15) * 4;    // 0..60

    const int tm = (tid >> 4) * TM;      // 0..60
    const int tn = (tid & 15) * TN;      // 0..60

    float acc[TM][TN];
#pragma unroll
    for (int i = 0; i < TM; i++)
#pragma unroll
        for (int j = 0; j < TN; j++) acc[i][j] = 0.0f;

    const float* Aptr = A + (size_t)(m0 + a_row) * K + a_col;
    const float* Bptr = Bw + (size_t)b_row * N + n0 + b_col;

    for (int k0 = 0; k0 < K; k0 += BK) {
        float4 av = *(const float4*)(Aptr + k0);
        As[a_col + 0][a_row] = av.x;
        As[a_col + 1][a_row] = av.y;
        As[a_col + 2][a_row] = av.z;
        As[a_col + 3][a_row] = av.w;
        *(float4*)&Bs[b_row][b_col] = *(const float4*)(Bptr + (size_t)k0 * N);
        __syncthreads();

#pragma unroll
        for (int k = 0; k < BK; k++) {
            float4 a4 = *(const float4*)&As[k][tm];
            float4 b4 = *(const float4*)&Bs[k][tn];
            float ar[4] = {a4.x, a4.y, a4.z, a4.w};
            float br[4] = {b4.x, b4.y, b4.z, b4.w};
#pragma unroll
            for (int i = 0; i < 4; i++)
#pragma unroll
                for (int j = 0; j < 4; j++)
                    acc[i][j] = fmaf(ar[i], br[j], acc[i][j]);
        }
        __syncthreads();
    }

    float4 bb = *(const float4*)(bias + n0 + tn);
#pragma unroll
    for (int i = 0; i < TM; i++) {
        float4 o;
        o.x = acc[i][0] + bb.x;
        o.y = acc[i][1] + bb.y;
        o.z = acc[i][2] + bb.z;
        o.w = acc[i][3] + bb.w;
        *(float4*)(C + (size_t)(m0 + tm + i) * N + n0 + tn) = o;
    }
}

// Fallback (shapes not divisible) — correctness safety net only.
__global__ void indrnn_gemm_naive(
    const float* __restrict__ A, const float* __restrict__ Bw,
    const float* __restrict__ bias, float* __restrict__ C,
    int M, int N, int K)
{
    int idx = blockIdx.x * blockDim.x + threadIdx.x;
    if (idx >= M * N) return;
    int m = idx / N, n = idx % N;
    float s = bias[n];
    for (int k = 0; k < K; k++) s = fmaf(A[(size_t)m * K + k], Bw[(size_t)k * N + n], s);
    C[idx] = s;
}

// Scan: one thread per (b,u) chain. 8 independent timestep loads issued per
// iteration so the dependent chain is only the FMA+ReLU, not the memory latency.
__global__ __launch_bounds__(256) void indrnn_scan(
    float* __restrict__ out,       // [B, T, U] holding proj; rewritten with h
    const float* __restrict__ h0,  // [B, U]
    const float* __restrict__ u,   // [U]
    int B, int T, int U)
{
    int idx = blockIdx.x * blockDim.x + threadIdx.x;
    if (idx >= B * U) return;
    int b = idx / U;
    int j = idx - b * U;

    float uc = fminf(fmaxf(u[j], 0.0f), 1.0f);
    float h = h0[idx];
    float* p = out + (size_t)b * T * U + j;
    const size_t s = (size_t)U;

    int t = 0;
    for (; t + 8 <= T; t += 8) {
        float v0 = p[0 * s], v1 = p[1 * s], v2 = p[2 * s], v3 = p[3 * s];
        float v4 = p[4 * s], v5 = p[5 * s], v6 = p[6 * s], v7 = p[7 * s];
        h = fmaxf(fmaf(h, uc, v0), 0.0f); p[0 * s] = h;
        h = fmaxf(fmaf(h, uc, v1), 0.0f); p[1 * s] = h;
        h = fmaxf(fmaf(h, uc, v2), 0.0f); p[2 * s] = h;
        h = fmaxf(fmaf(h, uc, v3), 0.0f); p[3 * s] = h;
        h = fmaxf(fmaf(h, uc, v4), 0.0f); p[4 * s] = h;
        h = fmaxf(fmaf(h, uc, v5), 0.0f); p[5 * s] = h;
        h = fmaxf(fmaf(h, uc, v6), 0.0f); p[6 * s] = h;
        h = fmaxf(fmaf(h, uc, v7), 0.0f); p[7 * s] = h;
        p += 8 * s;
    }
    for (; t < T; t++) {
        float v = *p;
        h = fmaxf(fmaf(h, uc, v), 0.0f);
        *p = h;
        p += s;
    }
}

extern "C" void kernel_launch(void* const* d_in, const int* in_sizes, int n_in,
                              void* d_out, int out_size)
{
    const float* x  = (const float*)d_in[0];  // [B, T, D]
    const float* h0 = (const float*)d_in[1];  // [B, U]
    const float* W  = (const float*)d_in[2];  // [D, U]
    const float* u  = (const float*)d_in[3];  // [U]
    const float* bb = (const float*)d_in[4];  // [U]
    float* out = (float*)d_out;               // [B, T, U]

    const int U = in_sizes[3];
    const int B = in_sizes[1] / U;
    const int D = in_sizes[2] / U;
    const int T = in_sizes[0] / (B * D);

    const int M = B * T;      // 32768
    const int N = U;          // 512
    const int K = D;          // 256

    if ((M % BM == 0) && (N % BN == 0) && (K % BK == 0)) {
        dim3 grid(N / BN, M / BM);
        indrnn_gemm_bias<<<grid, 256>>>(x, W, bb, out, M, N, K);
    } else {
        int total = M * N;
        indrnn_gemm_naive<<<(total + 255) / 256, 256>>>(x, W, bb, out, M, N, K);
    }

    int chains = B * U;
    indrnn_scan<<<(chains + 255) / 256, 256>>>(out, h0, u, B, T, U);
}

// round 3
// speedup vs baseline: 1.6724x; 1.6724x over previous
#include <cuda_runtime.h>
#include <cuda_bf16.h>
#include <cstdint>

// IndRNN on GB300 (sm_103a, but harness emits compute_103 baseline PTX -> no tcgen05).
//   proj = x @ W + b   via warp-level mma.sync bf16 hi/lo split (3 passes, fp32 accum)
//   h_t  = relu(proj_t + h_{t-1} * clip(u,0,1))  per-(b,u) scan, 16-deep MLP batching.
//
// Fast path shapes: M=B*T=32768, K=D=256, N=U=512 (guarded; naive fallback otherwise).

#define M_DIM 32768
#define K_DIM 256
#define U_DIM 512

// Pre-split bf16 scratch (static device arrays; no allocation).
__device__ __align__(16) __nv_bfloat16 g_x_hi[M_DIM * K_DIM];   // X  [M,K]
__device__ __align__(16) __nv_bfloat16 g_x_lo[M_DIM * K_DIM];
__device__ __align__(16) __nv_bfloat16 g_wt_hi[U_DIM * K_DIM];  // Wt [N,K] = W^T
__device__ __align__(16) __nv_bfloat16 g_wt_lo[U_DIM * K_DIM];

// ---------------------------------------------------------------------------
__device__ __forceinline__ uint32_t smem_u32(const void* p) {
    uint32_t a;
    asm("{ .reg .u64 t; cvta.to.shared.u64 t, %1; cvt.u32.u64 %0, t; }" : "=r"(a) : "l"(p));
    return a;
}
__device__ __forceinline__ void cp_async16(uint32_t saddr, const void* gptr) {
    asm volatile("cp.async.cg.shared.global [%0], [%1], 16;" :: "r"(saddr), "l"(gptr));
}
__device__ __forceinline__ void cp_commit() { asm volatile("cp.async.commit_group;"); }
__device__ __forceinline__ void cp_wait1() { asm volatile("cp.async.wait_group 1;"); }
__device__ __forceinline__ void cp_wait0() { asm volatile("cp.async.wait_group 0;"); }

__device__ __forceinline__ void mma16816(float* c, const uint32_t* a, uint32_t b0, uint32_t b1) {
    asm volatile(
        "mma.sync.aligned.m16n8k16.row.col.f32.bf16.bf16.f32 "
        "{%0,%1,%2,%3}, {%4,%5,%6,%7}, {%8,%9}, {%0,%1,%2,%3};"
        : "+f"(c[0]), "+f"(c[1]), "+f"(c[2]), "+f"(c[3])
        : "r"(a[0]), "r"(a[1]), "r"(a[2]), "r"(a[3]), "r"(b0), "r"(b1));
}

// ---------------------------------------------------------------------------
// Split kernels (run once per launch)
// ---------------------------------------------------------------------------
__global__ void xsplit_kernel(const float* __restrict__ X, int total4) {
    int i = blockIdx.x * blockDim.x + threadIdx.x;
    if (i >= total4) return;
    float4 v = ((const float4*)X)[i];
    __nv_bfloat16 h0 = __float2bfloat16(v.x), h1 = __float2bfloat16(v.y);
    __nv_bfloat16 h2 = __float2bfloat16(v.z), h3 = __float2bfloat16(v.w);
    __nv_bfloat16 l0 = __float2bfloat16(v.x - __bfloat162float(h0));
    __nv_bfloat16 l1 = __float2bfloat16(v.y - __bfloat162float(h1));
    __nv_bfloat16 l2 = __float2bfloat16(v.z - __bfloat162float(h2));
    __nv_bfloat16 l3 = __float2bfloat16(v.w - __bfloat162float(h3));
    uint2 hh, ll;
    hh.x = ((uint32_t)__bfloat16_as_ushort(h1) << 16) | __bfloat16_as_ushort(h0);
    hh.y = ((uint32_t)__bfloat16_as_ushort(h3) << 16) | __bfloat16_as_ushort(h2);
    ll.x = ((uint32_t)__bfloat16_as_ushort(l1) << 16) | __bfloat16_as_ushort(l0);
    ll.y = ((uint32_t)__bfloat16_as_ushort(l3) << 16) | __bfloat16_as_ushort(l2);
    ((uint2*)g_x_hi)[i] = hh;
    ((uint2*)g_x_lo)[i] = ll;
}

__global__ void wsplit_kernel(const float* __restrict__ W) {
    __shared__ float tile[32][33];
    int k0 = blockIdx.y * 32, u0 = blockIdx.x * 32;
    int tx = threadIdx.x, ty = threadIdx.y;  // 32 x 8
#pragma unroll
    for (int i = 0; i < 32; i += 8)
        tile[ty + i][tx] = W[(size_t)(k0 + ty + i) * U_DIM + u0 + tx];
    __syncthreads();
#pragma unroll
    for (int i = 0; i < 32; i += 8) {
        float v = tile[tx][ty + i];
        __nv_bfloat16 h = __float2bfloat16(v);
        __nv_bfloat16 l = __float2bfloat16(v - __bfloat162float(h));
        g_wt_hi[(size_t)(u0 + ty + i) * K_DIM + k0 + tx] = h;
        g_wt_lo[(size_t)(u0 + ty + i) * K_DIM + k0 + tx] = l;
    }
}

// ---------------------------------------------------------------------------
// HMMA GEMM: CTA tile 128(M) x 128(N), BK=32, 8 warps (4 along M x 2 along N),
// warp tile 32x64. Smem: 4 parts (Ahi,Alo,Bhi,Blo) x [128 rows x 32 bf16],
// row pitch 80B (conflict-free 20-bank stride), double-buffered cp.async.
// ---------------------------------------------------------------------------
#define APITCH 80
#define PART_BYTES (128 * APITCH)          // 10240
#define STAGE_BYTES (4 * PART_BYTES)       // 40960
#define GEMM_SMEM (2 * STAGE_BYTES)        // 81920

__global__ __launch_bounds__(256) void indrnn_gemm_mma(
    const float* __restrict__ bias, float* __restrict__ C)
{
    extern __shared__ __align__(16) char smem[];
    const uint32_t sbase = smem_u32(smem);

    const int tid = threadIdx.x;
    const int lane = tid & 31, warp = tid >> 5;
    const int wm = (warp & 3) * 32;        // warp M offset in CTA tile
    const int wn = (warp >> 2) * 64;       // warp N offset
    const int g = lane >> 2, tig = lane & 3;

    const int n0 = blockIdx.x * 128;
    const int m0 = blockIdx.y * 128;

    // ---- stage loader: 2048 x 16B chunks, 8 per thread
    auto load_stage = [&](int stage, int k0) {
        const uint32_t s0 = sbase + stage * STAGE_BYTES;
#pragma unroll
        for (int part = 0; part < 4; part++) {
            const __nv_bfloat16* gbase =
                (part == 0) ? g_x_hi : (part == 1) ? g_x_lo :
                (part == 2) ? g_wt_hi : g_wt_lo;
            const int row0 = (part < 2) ? m0 : n0;
#pragma unroll
            for (int j = 0; j < 2; j++) {
                int c = tid + j * 256;     // 0..511
                int r = c >> 2, unit = c & 3;
                const __nv_bfloat16* gp =
                    gbase + (size_t)(row0 + r) * K_DIM + k0 + unit * 8;
                cp_async16(s0 + part * PART_BYTES + r * APITCH + unit * 16, gp);
            }
        }
    };

    float acc[2][8][4];
#pragma unroll
    for (int ms = 0; ms < 2; ms++)
#pragma unroll
        for (int ns = 0; ns < 8; ns++)
#pragma unroll
            for (int i = 0; i < 4; i++) acc[ms][ns][i] = 0.0f;

    load_stage(0, 0);
    cp_commit();

    const int NKT = K_DIM / 32;  // 8
    for (int kt = 0; kt < NKT; kt++) {
        if (kt + 1 < NKT) {
            load_stage((kt + 1) & 1, (kt + 1) * 32);
            cp_commit();
            cp_wait1();
        } else {
            cp_wait0();
        }
        __syncthreads();

        const char* st = smem + (kt & 1) * STAGE_BYTES;
        const char* sAh = st;
        const char* sAl = st + PART_BYTES;
        const char* sBh = st + 2 * PART_BYTES;
        const char* sBl = st + 3 * PART_BYTES;

#pragma unroll
        for (int ks = 0; ks < 2; ks++) {
            const int cb = ks * 32 + tig * 4;
            uint32_t ah[2][4], al[2][4];
#pragma unroll
            for (int ms = 0; ms < 2; ms++) {
                const int r = wm + ms * 16 + g;
                ah[ms][0] = *(const uint32_t*)(sAh + r * APITCH + cb);
                ah[ms][1] = *(const uint32_t*)(sAh + (r + 8) * APITCH + cb);
                ah[ms][2] = *(const uint32_t*)(sAh + r * APITCH + cb + 16);
                ah[ms][3] = *(const uint32_t*)(sAh + (r + 8) * APITCH + cb + 16);
                al[ms][0] = *(const uint32_t*)(sAl + r * APITCH + cb);
                al[ms][1] = *(const uint32_t*)(sAl + (r + 8) * APITCH + cb);
                al[ms][2] = *(const uint32_t*)(sAl + r * APITCH + cb + 16);
                al[ms][3] = *(const uint32_t*)(sAl + (r + 8) * APITCH + cb + 16);
            }
#pragma unroll
            for (int ns = 0; ns < 8; ns++) {
                const int br = wn + ns * 8 + g;
                uint32_t bh0 = *(const uint32_t*)(sBh + br * APITCH + cb);
                uint32_t bh1 = *(const uint32_t*)(sBh + br * APITCH + cb + 16);
                uint32_t bl0 = *(const uint32_t*)(sBl + br * APITCH + cb);
                uint32_t bl1 = *(const uint32_t*)(sBl + br * APITCH + cb + 16);
#pragma unroll
                for (int ms = 0; ms < 2; ms++) {
                    mma16816(acc[ms][ns], ah[ms], bh0, bh1);  // hi*hi
                    mma16816(acc[ms][ns], ah[ms], bl0, bl1);  // hi*lo
                    mma16816(acc[ms][ns], al[ms], bh0, bh1);  // lo*hi
                }
            }
        }
        __syncthreads();
    }

    // ---- epilogue: +bias, write f32 pairs
#pragma unroll
    for (int ns = 0; ns < 8; ns++) {
        const int n = n0 + wn + ns * 8 + 2 * tig;
        float2 bb = *(const float2*)(bias + n);
#pragma unroll
        for (int ms = 0; ms < 2; ms++) {
            const int m = m0 + wm + ms * 16 + g;
            float2 o0, o1;
            o0.x = acc[ms][ns][0] + bb.x;
            o0.y = acc[ms][ns][1] + bb.y;
            o1.x = acc[ms][ns][2] + bb.x;
            o1.y = acc[ms][ns][3] + bb.y;
            *(float2*)(C + (size_t)m * U_DIM + n) = o0;
            *(float2*)(C + (size_t)(m + 8) * U_DIM + n) = o1;
        }
    }
}

// ---------------------------------------------------------------------------
// Fallback SIMT GEMM for unexpected shapes (correctness net).
// ---------------------------------------------------------------------------
__global__ void indrnn_gemm_naive(
    const float* __restrict__ A, const float* __restrict__ Bw,
    const float* __restrict__ bias, float* __restrict__ Cc,
    int M, int N, int K)
{
    int idx = blockIdx.x * blockDim.x + threadIdx.x;
    if (idx >= M * N) return;
    int m = idx / N, n = idx % N;
    float s = bias[n];
    for (int k = 0; k < K; k++) s = fmaf(A[(size_t)m * K + k], Bw[(size_t)k * N + n], s);
    Cc[idx] = s;
}

// ---------------------------------------------------------------------------
// Scan: one thread per (b,u) chain, 16-deep batching; __ldcg keeps L2 residency.
// ---------------------------------------------------------------------------
__global__ __launch_bounds__(256) void indrnn_scan(
    float* __restrict__ out, const float* __restrict__ h0,
    const float* __restrict__ u, int B, int T, int U)
{
    int idx = blockIdx.x * blockDim.x + threadIdx.x;
    if (idx >= B * U) return;
    int b = idx / U;
    int j = idx - b * U;

    float uc = fminf(fmaxf(u[j], 0.0f), 1.0f);
    float h = h0[idx];
    float* p = out + (size_t)b * T * U + j;
    const size_t st = (size_t)U;

    int t = 0;
    for (; t + 16 <= T; t += 16) {
        float v[16];
#pragma unroll
        for (int i = 0; i < 16; i++) v[i] = __ldcg(p + i * st);
#pragma unroll
        for (int i = 0; i < 16; i++) {
            h = fmaxf(fmaf(h, uc, v[i]), 0.0f);
            p[i * st] = h;
        }
        p += 16 * st;
    }
    for (; t < T; t++) {
        float v = __ldcg(p);
        h = fmaxf(fmaf(h, uc, v), 0.0f);
        *p = h;
        p += st;
    }
}

// ---------------------------------------------------------------------------
extern "C" void kernel_launch(void* const* d_in, const int* in_sizes, int n_in,
                              void* d_out, int out_size)
{
    const float* x  = (const float*)d_in[0];  // [B, T, D]
    const float* h0 = (const float*)d_in[1];  // [B, U]
    const float* W  = (const float*)d_in[2];  // [D, U]
    const float* u  = (const float*)d_in[3];  // [U]
    const float* bb = (const float*)d_in[4];  // [U]
    float* out = (float*)d_out;               // [B, T, U]

    const int U = in_sizes[3];
    const int B = in_sizes[1] / U;
    const int D = in_sizes[2] / U;
    const int T = in_sizes[0] / (B * D);

    const int M = B * T;
    const int N = U;
    const int K = D;

    if (M == M_DIM && N == U_DIM && K == K_DIM) {
        int total4 = M_DIM * K_DIM / 4;
        xsplit_kernel<<<(total4 + 255) / 256, 256>>>(x, total4);
        wsplit_kernel<<<dim3(U_DIM / 32, K_DIM / 32), dim3(32, 8)>>>(W);
        cudaFuncSetAttribute(indrnn_gemm_mma,
                             cudaFuncAttributeMaxDynamicSharedMemorySize, GEMM_SMEM);
        indrnn_gemm_mma<<<dim3(N / 128, M / 128), 256, GEMM_SMEM>>>(bb, out);
    } else {
        int total = M * N;
        indrnn_gemm_naive<<<(total + 255) / 256, 256>>>(x, W, bb, out, M, N, K);
    }

    int chains = B * U;
    indrnn_scan<<<(chains + 255) / 256, 256>>>(out, h0, u, B, T, U);
}

// round 4
// speedup vs baseline: 2.3238x; 1.3895x over previous
#include <cuda_runtime.h>
#include <cuda_bf16.h>
#include <cstdint>

// IndRNN (sm_103a, baseline-PTX constraint -> warp mma.sync, no tcgen05):
//   proj = x @ W + b : HMMA bf16 hi/lo 3-pass GEMM; X fp32 loaded directly and
//                      split in-registers (no x-split prepass; saves 96MB traffic).
//   scan: h_t = relu(proj_t + h_{t-1}*clip(u,0,1)), depth-32 MLP batching.

#define M_DIM 32768
#define K_DIM 256
#define U_DIM 512

__device__ __align__(16) __nv_bfloat16 g_wt_hi[U_DIM * K_DIM];  // Wt [N,K] = W^T
__device__ __align__(16) __nv_bfloat16 g_wt_lo[U_DIM * K_DIM];

// ---------------------------------------------------------------------------
__device__ __forceinline__ uint32_t smem_u32(const void* p) {
    uint32_t a;
    asm("{ .reg .u64 t; cvta.to.shared.u64 t, %1; cvt.u32.u64 %0, t; }" : "=r"(a) : "l"(p));
    return a;
}
__device__ __forceinline__ void cp_async16(uint32_t saddr, const void* gptr) {
    asm volatile("cp.async.cg.shared.global [%0], [%1], 16;" :: "r"(saddr), "l"(gptr));
}
__device__ __forceinline__ void cp_commit() { asm volatile("cp.async.commit_group;"); }
__device__ __forceinline__ void cp_wait0() { asm volatile("cp.async.wait_group 0;"); }

__device__ __forceinline__ void mma16816(float* c, const uint32_t* a, uint32_t b0, uint32_t b1) {
    asm volatile(
        "mma.sync.aligned.m16n8k16.row.col.f32.bf16.bf16.f32 "
        "{%0,%1,%2,%3}, {%4,%5,%6,%7}, {%8,%9}, {%0,%1,%2,%3};"
        : "+f"(c[0]), "+f"(c[1]), "+f"(c[2]), "+f"(c[3])
        : "r"(a[0]), "r"(a[1]), "r"(a[2]), "r"(a[3]), "r"(b0), "r"(b1));
}

__device__ __forceinline__ void split2(float x, float y, uint32_t& hp, uint32_t& lp) {
    __nv_bfloat16 hx = __float2bfloat16(x), hy = __float2bfloat16(y);
    __nv_bfloat16 lx = __float2bfloat16(x - __bfloat162float(hx));
    __nv_bfloat16 ly = __float2bfloat16(y - __bfloat162float(hy));
    hp = ((uint32_t)__bfloat16_as_ushort(hy) << 16) | __bfloat16_as_ushort(hx);
    lp = ((uint32_t)__bfloat16_as_ushort(ly) << 16) | __bfloat16_as_ushort(lx);
}

// ---------------------------------------------------------------------------
// W transpose + bf16 hi/lo split (once per launch; W is only 0.5 MB)
// ---------------------------------------------------------------------------
__global__ void wsplit_kernel(const float* __restrict__ W) {
    __shared__ float tile[32][33];
    int k0 = blockIdx.y * 32, u0 = blockIdx.x * 32;
    int tx = threadIdx.x, ty = threadIdx.y;  // 32 x 8
#pragma unroll
    for (int i = 0; i < 32; i += 8)
        tile[ty + i][tx] = W[(size_t)(k0 + ty + i) * U_DIM + u0 + tx];
    __syncthreads();
#pragma unroll
    for (int i = 0; i < 32; i += 8) {
        float v = tile[tx][ty + i];
        __nv_bfloat16 h = __float2bfloat16(v);
        __nv_bfloat16 l = __float2bfloat16(v - __bfloat162float(h));
        g_wt_hi[(size_t)(u0 + ty + i) * K_DIM + k0 + tx] = h;
        g_wt_lo[(size_t)(u0 + ty + i) * K_DIM + k0 + tx] = l;
    }
}

// ---------------------------------------------------------------------------
// HMMA GEMM: CTA 128x128, BK=32, 8 warps (4M x 2N), warp tile 32x64.
// Smem stage: parts {A_hi, A_lo, B_hi, B_lo}, each 128 rows x 32 bf16, pitch 80B.
// A: LDG fp32 -> register split -> STS (pipelined one stage ahead).
// B: cp.async from pre-split g_wt scratch.
// ---------------------------------------------------------------------------
#define APITCH 80
#define PART_BYTES (128 * APITCH)
#define STAGE_BYTES (4 * PART_BYTES)
#define GEMM_SMEM (2 * STAGE_BYTES)

__global__ __launch_bounds__(256, 1) void indrnn_gemm_mma(
    const float* __restrict__ X, const float* __restrict__ bias, float* __restrict__ C)
{
    extern __shared__ __align__(16) char smem[];
    const uint32_t sbase = smem_u32(smem);

    const int tid = threadIdx.x;
    const int lane = tid & 31, warp = tid >> 5;
    const int wm = (warp & 3) * 32;
    const int wn = (warp >> 2) * 64;
    const int g = lane >> 2, tig = lane & 3;

    const int n0 = blockIdx.x * 128;
    const int m0 = blockIdx.y * 128;

    // A-load geometry: 1024 float4 chunks per stage, 4 per thread
    int ar[4], ac4[4];
#pragma unroll
    for (int j = 0; j < 4; j++) {
        int q = tid + j * 256;
        ar[j] = q >> 3;        // row 0..127
        ac4[j] = q & 7;        // float4 index in row (k = c4*4)
    }

    auto ldgA = [&](int k0, float4* regs) {
#pragma unroll
        for (int j = 0; j < 4; j++)
            regs[j] = *(const float4*)&X[(size_t)(m0 + ar[j]) * K_DIM + k0 + ac4[j] * 4];
    };
    auto stsA = [&](int buf, const float4* regs) {
        char* s0 = smem + buf * STAGE_BYTES;
#pragma unroll
        for (int j = 0; j < 4; j++) {
            uint2 hp, lp;
            split2(regs[j].x, regs[j].y, hp.x, lp.x);
            split2(regs[j].z, regs[j].w, hp.y, lp.y);
            int off = ar[j] * APITCH + ac4[j] * 8;
            *(uint2*)(s0 + off) = hp;
            *(uint2*)(s0 + PART_BYTES + off) = lp;
        }
    };
    auto cpB = [&](int buf, int k0) {
        const uint32_t s0 = sbase + buf * STAGE_BYTES + 2 * PART_BYTES;
#pragma unroll
        for (int part = 0; part < 2; part++) {
            const __nv_bfloat16* gb = part ? g_wt_lo : g_wt_hi;
#pragma unroll
            for (int j = 0; j < 2; j++) {
                int c = tid + j * 256;         // 0..511
                int r = c >> 2, unit = c & 3;
                cp_async16(s0 + part * PART_BYTES + r * APITCH + unit * 16,
                           gb + (size_t)(n0 + r) * K_DIM + k0 + unit * 8);
            }
        }
    };

    float acc[2][8][4];
#pragma unroll
    for (int ms = 0; ms < 2; ms++)
#pragma unroll
        for (int ns = 0; ns < 8; ns++)
#pragma unroll
            for (int i = 0; i < 4; i++) acc[ms][ns][i] = 0.0f;

    const int NKT = K_DIM / 32;  // 8
    float4 regs[4];

    // Prologue: fill stage 0, prefetch A(1) into regs
    ldgA(0, regs);
    cpB(0, 0);
    cp_commit();
    stsA(0, regs);
    ldgA(32, regs);
    cp_wait0();
    __syncthreads();

    for (int kt = 0; kt < NKT; kt++) {
        const int buf = kt & 1;

        // Fill next stage (other buffer was released by last iteration's sync)
        if (kt + 1 < NKT) {
            stsA(buf ^ 1, regs);
            cpB(buf ^ 1, (kt + 1) * 32);
            cp_commit();
        }
        if (kt + 2 < NKT) ldgA((kt + 2) * 32, regs);

        const char* st = smem + buf * STAGE_BYTES;
        const char* sAh = st;
        const char* sAl = st + PART_BYTES;
        const char* sBh = st + 2 * PART_BYTES;
        const char* sBl = st + 3 * PART_BYTES;

#pragma unroll
        for (int ks = 0; ks < 2; ks++) {
            const int cb = ks * 32 + tig * 4;
            uint32_t ah[2][4], al[2][4];
#pragma unroll
            for (int ms = 0; ms < 2; ms++) {
                const int r = wm + ms * 16 + g;
                ah[ms][0] = *(const uint32_t*)(sAh + r * APITCH + cb);
                ah[ms][1] = *(const uint32_t*)(sAh + (r + 8) * APITCH + cb);
                ah[ms][2] = *(const uint32_t*)(sAh + r * APITCH + cb + 16);
                ah[ms][3] = *(const uint32_t*)(sAh + (r + 8) * APITCH + cb + 16);
                al[ms][0] = *(const uint32_t*)(sAl + r * APITCH + cb);
                al[ms][1] = *(const uint32_t*)(sAl + (r + 8) * APITCH + cb);
                al[ms][2] = *(const uint32_t*)(sAl + r * APITCH + cb + 16);
                al[ms][3] = *(const uint32_t*)(sAl + (r + 8) * APITCH + cb + 16);
            }
#pragma unroll
            for (int ns = 0; ns < 8; ns++) {
                const int br = wn + ns * 8 + g;
                uint32_t bh0 = *(const uint32_t*)(sBh + br * APITCH + cb);
                uint32_t bh1 = *(const uint32_t*)(sBh + br * APITCH + cb + 16);
                uint32_t bl0 = *(const uint32_t*)(sBl + br * APITCH + cb);
                uint32_t bl1 = *(const uint32_t*)(sBl + br * APITCH + cb + 16);
#pragma unroll
                for (int ms = 0; ms < 2; ms++) {
                    mma16816(acc[ms][ns], ah[ms], bh0, bh1);
                    mma16816(acc[ms][ns], ah[ms], bl0, bl1);
                    mma16816(acc[ms][ns], al[ms], bh0, bh1);
                }
            }
        }
        if (kt + 1 < NKT) cp_wait0();
        __syncthreads();
    }

    // Epilogue: +bias, f32 pair stores
#pragma unroll
    for (int ns = 0; ns < 8; ns++) {
        const int n = n0 + wn + ns * 8 + 2 * tig;
        float2 bb = *(const float2*)(bias + n);
#pragma unroll
        for (int ms = 0; ms < 2; ms++) {
            const int m = m0 + wm + ms * 16 + g;
            float2 o0, o1;
            o0.x = acc[ms][ns][0] + bb.x;
            o0.y = acc[ms][ns][1] + bb.y;
            o1.x = acc[ms][ns][2] + bb.x;
            o1.y = acc[ms][ns][3] + bb.y;
            *(float2*)(C + (size_t)m * U_DIM + n) = o0;
            *(float2*)(C + (size_t)(m + 8) * U_DIM + n) = o1;
        }
    }
}

// ---------------------------------------------------------------------------
__global__ void indrnn_gemm_naive(
    const float* __restrict__ A, const float* __restrict__ Bw,
    const float* __restrict__ bias, float* __restrict__ Cc,
    int M, int N, int K)
{
    int idx = blockIdx.x * blockDim.x + threadIdx.x;
    if (idx >= M * N) return;
    int m = idx / N, n = idx % N;
    float s = bias[n];
    for (int k = 0; k < K; k++) s = fmaf(A[(size_t)m * K + k], Bw[(size_t)k * N + n], s);
    Cc[idx] = s;
}

// ---------------------------------------------------------------------------
// Scan: one thread per (b,u) chain, depth-32 batching (32 LDG in flight/thread).
// ---------------------------------------------------------------------------
__global__ __launch_bounds__(128) void indrnn_scan(
    float* __restrict__ out, const float* __restrict__ h0,
    const float* __restrict__ u, int B, int T, int U)
{
    int idx = blockIdx.x * blockDim.x + threadIdx.x;
    if (idx >= B * U) return;
    int b = idx / U;
    int j = idx - b * U;

    float uc = fminf(fmaxf(u[j], 0.0f), 1.0f);
    float h = h0[idx];
    float* p = out + (size_t)b * T * U + j;
    const size_t st = (size_t)U;

    int t = 0;
    for (; t + 32 <= T; t += 32) {
        float v[32];
#pragma unroll
        for (int i = 0; i < 32; i++) v[i] = __ldcg(p + i * st);
#pragma unroll
        for (int i = 0; i < 32; i++) {
            h = fmaxf(fmaf(h, uc, v[i]), 0.0f);
            p[i * st] = h;
        }
        p += 32 * st;
    }
    for (; t < T; t++) {
        float v = __ldcg(p);
        h = fmaxf(fmaf(h, uc, v), 0.0f);
        *p = h;
        p += st;
    }
}

// ---------------------------------------------------------------------------
extern "C" void kernel_launch(void* const* d_in, const int* in_sizes, int n_in,
                              void* d_out, int out_size)
{
    const float* x  = (const float*)d_in[0];
    const float* h0 = (const float*)d_in[1];
    const float* W  = (const float*)d_in[2];
    const float* u  = (const float*)d_in[3];
    const float* bb = (const float*)d_in[4];
    float* out = (float*)d_out;

    const int U = in_sizes[3];
    const int B = in_sizes[1] / U;
    const int D = in_sizes[2] / U;
    const int T = in_sizes[0] / (B * D);

    const int M = B * T;
    const int N = U;
    const int K = D;

    if (M == M_DIM && N == U_DIM && K == K_DIM) {
        wsplit_kernel<<<dim3(U_DIM / 32, K_DIM / 32), dim3(32, 8)>>>(W);
        cudaFuncSetAttribute(indrnn_gemm_mma,
                             cudaFuncAttributeMaxDynamicSharedMemorySize, GEMM_SMEM);
        indrnn_gemm_mma<<<dim3(N / 128, M / 128), 256, GEMM_SMEM>>>(x, bb, out);
    } else {
        int total = M * N;
        indrnn_gemm_naive<<<(total + 255) / 256, 256>>>(x, W, bb, out, M, N, K);
    }

    int chains = B * U;
    indrnn_scan<<<(chains + 127) / 128, 128>>>(out, h0, u, B, T, U);
}

// round 5
// speedup vs baseline: 3.0301x; 1.3039x over previous
#include <cuda_runtime.h>
#include <cuda_bf16.h>
#include <cstdint>

// IndRNN (sm_103a under baseline-PTX constraint -> warp mma.sync, no tcgen05):
//   proj = x @ W + b : single-pass TF32 HMMA GEMM (cvt.rna on both operands,
//                      fp32 accumulate) — 2/3 the HMMA count of bf16 3-pass.
//   scan: h_t = relu(proj_t + h_{t-1}*clip(u,0,1)), depth-32 MLP batching.

#define M_DIM 32768
#define K_DIM 256
#define U_DIM 512

// W^T, tf32-rounded, [N,K] K-major scratch (0.5 MB).
__device__ __align__(16) float g_wt[U_DIM * K_DIM];

// ---------------------------------------------------------------------------
__device__ __forceinline__ uint32_t smem_u32(const void* p) {
    uint32_t a;
    asm("{ .reg .u64 t; cvta.to.shared.u64 t, %1; cvt.u32.u64 %0, t; }" : "=r"(a) : "l"(p));
    return a;
}
__device__ __forceinline__ void cp_async16(uint32_t saddr, const void* gptr) {
    asm volatile("cp.async.cg.shared.global [%0], [%1], 16;" :: "r"(saddr), "l"(gptr));
}
__device__ __forceinline__ void cp_commit() { asm volatile("cp.async.commit_group;"); }
__device__ __forceinline__ void cp_wait0() { asm volatile("cp.async.wait_group 0;"); }

__device__ __forceinline__ uint32_t f2tf32(float f) {
    uint32_t r;
    asm("cvt.rna.tf32.f32 %0, %1;" : "=r"(r) : "f"(f));
    return r;
}
__device__ __forceinline__ void mma16888(float* c, const uint32_t* a, uint32_t b0, uint32_t b1) {
    asm volatile(
        "mma.sync.aligned.m16n8k8.row.col.f32.tf32.tf32.f32 "
        "{%0,%1,%2,%3}, {%4,%5,%6,%7}, {%8,%9}, {%0,%1,%2,%3};"
        : "+f"(c[0]), "+f"(c[1]), "+f"(c[2]), "+f"(c[3])
        : "r"(a[0]), "r"(a[1]), "r"(a[2]), "r"(a[3]), "r"(b0), "r"(b1));
}

// ---------------------------------------------------------------------------
// W transpose + tf32 round (once per launch)
// ---------------------------------------------------------------------------
__global__ void wsplit_kernel(const float* __restrict__ W) {
    __shared__ float tile[32][33];
    int k0 = blockIdx.y * 32, u0 = blockIdx.x * 32;
    int tx = threadIdx.x, ty = threadIdx.y;  // 32 x 8
#pragma unroll
    for (int i = 0; i < 32; i += 8)
        tile[ty + i][tx] = W[(size_t)(k0 + ty + i) * U_DIM + u0 + tx];
    __syncthreads();
#pragma unroll
    for (int i = 0; i < 32; i += 8) {
        float v = tile[tx][ty + i];
        g_wt[(size_t)(u0 + ty + i) * K_DIM + k0 + tx] = __uint_as_float(f2tf32(v));
    }
}

// ---------------------------------------------------------------------------
// TF32 HMMA GEMM: CTA 128(M)x128(N), BK=32, 8 warps (4M x 2N), warp 32x64.
// Smem stage: A part + B part, each 128 rows x 32 f32, pitch 144B (36 floats):
// fragment banks = 4*g + tig -> conflict-free. Double-buffered.
// A: LDG fp32 -> cvt.rna.tf32 -> STS (one stage ahead). B: cp.async of g_wt.
// ---------------------------------------------------------------------------
#define APITCH 144
#define PART_BYTES (128 * APITCH)          // 18432
#define STAGE_BYTES (2 * PART_BYTES)       // 36864
#define GEMM_SMEM (2 * STAGE_BYTES)        // 73728

__global__ __launch_bounds__(256, 1) void indrnn_gemm_tf32(
    const float* __restrict__ X, const float* __restrict__ bias, float* __restrict__ C)
{
    extern __shared__ __align__(16) char smem[];
    const uint32_t sbase = smem_u32(smem);

    const int tid = threadIdx.x;
    const int lane = tid & 31, warp = tid >> 5;
    const int wm = (warp & 3) * 32;
    const int wn = (warp >> 2) * 64;
    const int g = lane >> 2, tig = lane & 3;

    const int n0 = blockIdx.x * 128;
    const int m0 = blockIdx.y * 128;

    // A geometry: 1024 float4 chunks/stage, 4 per thread
    int ar[4], ac4[4];
#pragma unroll
    for (int j = 0; j < 4; j++) {
        int q = tid + j * 256;
        ar[j] = q >> 3;
        ac4[j] = q & 7;
    }

    auto ldgA = [&](int k0, float4* regs) {
#pragma unroll
        for (int j = 0; j < 4; j++)
            regs[j] = *(const float4*)&X[(size_t)(m0 + ar[j]) * K_DIM + k0 + ac4[j] * 4];
    };
    auto stsA = [&](int buf, const float4* regs) {
        char* s0 = smem + buf * STAGE_BYTES;
#pragma unroll
        for (int j = 0; j < 4; j++) {
            uint4 t;
            t.x = f2tf32(regs[j].x);
            t.y = f2tf32(regs[j].y);
            t.z = f2tf32(regs[j].z);
            t.w = f2tf32(regs[j].w);
            *(uint4*)(s0 + ar[j] * APITCH + ac4[j] * 16) = t;
        }
    };
    auto cpB = [&](int buf, int k0) {
        const uint32_t s0 = sbase + buf * STAGE_BYTES + PART_BYTES;
#pragma unroll
        for (int j = 0; j < 4; j++) {
            int c = tid + j * 256;       // 0..1023
            int r = c >> 3, unit = c & 7;
            cp_async16(s0 + r * APITCH + unit * 16,
                       g_wt + (size_t)(n0 + r) * K_DIM + k0 + unit * 4);
        }
    };

    float acc[2][8][4];
#pragma unroll
    for (int ms = 0; ms < 2; ms++)
#pragma unroll
        for (int ns = 0; ns < 8; ns++)
#pragma unroll
            for (int i = 0; i < 4; i++) acc[ms][ns][i] = 0.0f;

    const int NKT = K_DIM / 32;  // 8
    float4 regs[4];

    // Prologue
    ldgA(0, regs);
    cpB(0, 0);
    cp_commit();
    stsA(0, regs);
    ldgA(32, regs);
    cp_wait0();
    __syncthreads();

    for (int kt = 0; kt < NKT; kt++) {
        const int buf = kt & 1;

        if (kt + 1 < NKT) {
            stsA(buf ^ 1, regs);
            cpB(buf ^ 1, (kt + 1) * 32);
            cp_commit();
        }
        if (kt + 2 < NKT) ldgA((kt + 2) * 32, regs);

        const char* sA = smem + buf * STAGE_BYTES;
        const char* sB = sA + PART_BYTES;

#pragma unroll
        for (int ks = 0; ks < 4; ks++) {
            const int cb = ks * 32 + tig * 4;   // byte offset of col (ks*8 + tig)
            uint32_t a[2][4];
#pragma unroll
            for (int ms = 0; ms < 2; ms++) {
                const int r = wm + ms * 16 + g;
                a[ms][0] = *(const uint32_t*)(sA + r * APITCH + cb);
                a[ms][1] = *(const uint32_t*)(sA + (r + 8) * APITCH + cb);
                a[ms][2] = *(const uint32_t*)(sA + r * APITCH + cb + 16);
                a[ms][3] = *(const uint32_t*)(sA + (r + 8) * APITCH + cb + 16);
            }
#pragma unroll
            for (int ns = 0; ns < 8; ns++) {
                const int br = wn + ns * 8 + g;
                uint32_t b0 = *(const uint32_t*)(sB + br * APITCH + cb);
                uint32_t b1 = *(const uint32_t*)(sB + br * APITCH + cb + 16);
#pragma unroll
                for (int ms = 0; ms < 2; ms++)
                    mma16888(acc[ms][ns], a[ms], b0, b1);
            }
        }
        if (kt + 1 < NKT) cp_wait0();
        __syncthreads();
    }

    // Epilogue: +bias, f32 pair stores
#pragma unroll
    for (int ns = 0; ns < 8; ns++) {
        const int n = n0 + wn + ns * 8 + 2 * tig;
        float2 bb = *(const float2*)(bias + n);
#pragma unroll
        for (int ms = 0; ms < 2; ms++) {
            const int m = m0 + wm + ms * 16 + g;
            float2 o0, o1;
            o0.x = acc[ms][ns][0] + bb.x;
            o0.y = acc[ms][ns][1] + bb.y;
            o1.x = acc[ms][ns][2] + bb.x;
            o1.y = acc[ms][ns][3] + bb.y;
            *(float2*)(C + (size_t)m * U_DIM + n) = o0;
            *(float2*)(C + (size_t)(m + 8) * U_DIM + n) = o1;
        }
    }
}

// ---------------------------------------------------------------------------
__global__ void indrnn_gemm_naive(
    const float* __restrict__ A, const float* __restrict__ Bw,
    const float* __restrict__ bias, float* __restrict__ Cc,
    int M, int N, int K)
{
    int idx = blockIdx.x * blockDim.x + threadIdx.x;
    if (idx >= M * N) return;
    int m = idx / N, n = idx % N;
    float s = bias[n];
    for (int k = 0; k < K; k++) s = fmaf(A[(size_t)m * K + k], Bw[(size_t)k * N + n], s);
    Cc[idx] = s;
}

// ---------------------------------------------------------------------------
// Scan: one thread per (b,u) chain, depth-32 batching.
// ---------------------------------------------------------------------------
__global__ __launch_bounds__(128) void indrnn_scan(
    float* __restrict__ out, const float* __restrict__ h0,
    const float* __restrict__ u, int B, int T, int U)
{
    int idx = blockIdx.x * blockDim.x + threadIdx.x;
    if (idx >= B * U) return;
    int b = idx / U;
    int j = idx - b * U;

    float uc = fminf(fmaxf(u[j], 0.0f), 1.0f);
    float h = h0[idx];
    float* p = out + (size_t)b * T * U + j;
    const size_t st = (size_t)U;

    int t = 0;
    for (; t + 32 <= T; t += 32) {
        float v[32];
#pragma unroll
        for (int i = 0; i < 32; i++) v[i] = __ldcg(p + i * st);
#pragma unroll
        for (int i = 0; i < 32; i++) {
            h = fmaxf(fmaf(h, uc, v[i]), 0.0f);
            p[i * st] = h;
        }
        p += 32 * st;
    }
    for (; t < T; t++) {
        float v = __ldcg(p);
        h = fmaxf(fmaf(h, uc, v), 0.0f);
        *p = h;
        p += st;
    }
}

// ---------------------------------------------------------------------------
extern "C" void kernel_launch(void* const* d_in, const int* in_sizes, int n_in,
                              void* d_out, int out_size)
{
    const float* x  = (const float*)d_in[0];
    const float* h0 = (const float*)d_in[1];
    const float* W  = (const float*)d_in[2];
    const float* u  = (const float*)d_in[3];
    const float* bb = (const float*)d_in[4];
    float* out = (float*)d_out;

    const int U = in_sizes[3];
    const int B = in_sizes[1] / U;
    const int D = in_sizes[2] / U;
    const int T = in_sizes[0] / (B * D);

    const int M = B * T;
    const int N = U;
    const int K = D;

    if (M == M_DIM && N == U_DIM && K == K_DIM) {
        wsplit_kernel<<<dim3(U_DIM / 32, K_DIM / 32), dim3(32, 8)>>>(W);
        cudaFuncSetAttribute(indrnn_gemm_tf32,
                             cudaFuncAttributeMaxDynamicSharedMemorySize, GEMM_SMEM);
        indrnn_gemm_tf32<<<dim3(N / 128, M / 128), 256, GEMM_SMEM>>>(x, bb, out);
    } else {
        int total = M * N;
        indrnn_gemm_naive<<<(total + 255) / 256, 256>>>(x, W, bb, out, M, N, K);
    }

    int chains = B * U;
    indrnn_scan<<<(chains + 127) / 128, 128>>>(out, h0, u, B, T, U);
}

// round 9
// speedup vs baseline: 3.6178x; 1.1939x over previous
#include <cuda_runtime.h>
#include <cuda_bf16.h>
#include <cstdint>

// IndRNN (sm_103a, baseline-PTX -> warp mma.sync tf32):
//   proj = x @ W + b : single-pass TF32 HMMA GEMM.
//     A (X) : LDG fp32 -> cvt.rna.tf32 -> STS, [m][k] pitch 144.
//     B (W) : cp.async native [k][n] slice, pitch 544 (banks 8*tig+g, conflict-
//             free), cvt.rna.tf32 applied after LDS (zero-mean rounding).
//     No W prepass, no scratch.
//   scan: h_t = relu(proj_t + h_{t-1}*clip(u,0,1)); depth-32 software-pipelined.

#define M_DIM 32768
#define K_DIM 256
#define U_DIM 512

// ---------------------------------------------------------------------------
__device__ __forceinline__ uint32_t smem_u32(const void* p) {
    uint32_t a;
    asm("{ .reg .u64 t; cvta.to.shared.u64 t, %1; cvt.u32.u64 %0, t; }" : "=r"(a) : "l"(p));
    return a;
}
__device__ __forceinline__ void cp_async16(uint32_t saddr, const void* gptr) {
    asm volatile("cp.async.cg.shared.global [%0], [%1], 16;" :: "r"(saddr), "l"(gptr));
}
__device__ __forceinline__ void cp_commit() { asm volatile("cp.async.commit_group;"); }
__device__ __forceinline__ void cp_wait0() { asm volatile("cp.async.wait_group 0;"); }

__device__ __forceinline__ uint32_t f2tf32(float f) {
    uint32_t r;
    asm("cvt.rna.tf32.f32 %0, %1;" : "=r"(r) : "f"(f));
    return r;
}
__device__ __forceinline__ void mma16888(float* c, const uint32_t* a, uint32_t b0, uint32_t b1) {
    asm volatile(
        "mma.sync.aligned.m16n8k8.row.col.f32.tf32.tf32.f32 "
        "{%0,%1,%2,%3}, {%4,%5,%6,%7}, {%8,%9}, {%0,%1,%2,%3};"
        : "+f"(c[0]), "+f"(c[1]), "+f"(c[2]), "+f"(c[3])
        : "r"(a[0]), "r"(a[1]), "r"(a[2]), "r"(a[3]), "r"(b0), "r"(b1));
}

// ---------------------------------------------------------------------------
// TF32 HMMA GEMM: CTA 128(M)x128(N), BK=32, 8 warps (4M x 2N), warp 32x64.
// A smem: 128 rows(m) x 32 f32(k), pitch 144B. B smem: 32 rows(k) x 128 f32(n),
// pitch 544B. Double-buffered; A one stage ahead via LDG->cvt->STS.
// ---------------------------------------------------------------------------
#define APITCH 144
#define BPITCH 544
#define PART_A (128 * APITCH)              // 18432
#define PART_B (32 * BPITCH)               // 17408
#define STAGE_BYTES (PART_A + PART_B)      // 35840
#define GEMM_SMEM (2 * STAGE_BYTES)        // 71680

__global__ __launch_bounds__(256) void indrnn_gemm_tf32(
    const float* __restrict__ X, const float* __restrict__ W,
    const float* __restrict__ bias, float* __restrict__ C)
{
    extern __shared__ __align__(16) char smem[];
    const uint32_t sbase = smem_u32(smem);

    const int tid = threadIdx.x;
    const int lane = tid & 31, warp = tid >> 5;
    const int wm = (warp & 3) * 32;
    const int wn = (warp >> 2) * 64;
    const int g = lane >> 2, tig = lane & 3;

    const int n0 = blockIdx.x * 128;
    const int m0 = blockIdx.y * 128;

    // A geometry: 1024 float4 chunks/stage, 4 per thread
    int ar[4], ac4[4];
#pragma unroll
    for (int j = 0; j < 4; j++) {
        int q = tid + j * 256;
        ar[j] = q >> 3;
        ac4[j] = q & 7;
    }

    auto ldgA = [&](int k0, float4* regs) {
#pragma unroll
        for (int j = 0; j < 4; j++)
            regs[j] = *(const float4*)&X[(size_t)(m0 + ar[j]) * K_DIM + k0 + ac4[j] * 4];
    };
    auto stsA = [&](int buf, const float4* regs) {
        char* s0 = smem + buf * STAGE_BYTES;
#pragma unroll
        for (int j = 0; j < 4; j++) {
            uint4 t;
            t.x = f2tf32(regs[j].x);
            t.y = f2tf32(regs[j].y);
            t.z = f2tf32(regs[j].z);
            t.w = f2tf32(regs[j].w);
            *(uint4*)(s0 + ar[j] * APITCH + ac4[j] * 16) = t;
        }
    };
    // B: W[k0+r][n0 + 4*unit ..] native fp32, 32 rows x 32 chunks of 16B
    auto cpB = [&](int buf, int k0) {
        const uint32_t s0 = sbase + buf * STAGE_BYTES + PART_A;
#pragma unroll
        for (int j = 0; j < 4; j++) {
            int c = tid + j * 256;       // 0..1023
            int r = c >> 5, unit = c & 31;
            cp_async16(s0 + r * BPITCH + unit * 16,
                       W + (size_t)(k0 + r) * U_DIM + n0 + unit * 4);
        }
    };

    float acc[2][8][4];
#pragma unroll
    for (int ms = 0; ms < 2; ms++)
#pragma unroll
        for (int ns = 0; ns < 8; ns++)
#pragma unroll
            for (int i = 0; i < 4; i++) acc[ms][ns][i] = 0.0f;

    const int NKT = K_DIM / 32;  // 8
    float4 regs[4];

    // Prologue
    ldgA(0, regs);
    cpB(0, 0);
    cp_commit();
    stsA(0, regs);
    ldgA(32, regs);
    cp_wait0();
    __syncthreads();

    for (int kt = 0; kt < NKT; kt++) {
        const int buf = kt & 1;

        if (kt + 1 < NKT) {
            stsA(buf ^ 1, regs);
            cpB(buf ^ 1, (kt + 1) * 32);
            cp_commit();
        }
        if (kt + 2 < NKT) ldgA((kt + 2) * 32, regs);

        const char* sA = smem + buf * STAGE_BYTES;
        const char* sB = sA + PART_A;

#pragma unroll
        for (int ks = 0; ks < 4; ks++) {
            const int cb = ks * 32 + tig * 4;   // A col byte offset (k)
            uint32_t a[2][4];
#pragma unroll
            for (int ms = 0; ms < 2; ms++) {
                const int r = wm + ms * 16 + g;
                a[ms][0] = *(const uint32_t*)(sA + r * APITCH + cb);
                a[ms][1] = *(const uint32_t*)(sA + (r + 8) * APITCH + cb);
                a[ms][2] = *(const uint32_t*)(sA + r * APITCH + cb + 16);
                a[ms][3] = *(const uint32_t*)(sA + (r + 8) * APITCH + cb + 16);
            }
            // B row base: k = ks*8 + tig, n = wn + g (+ ns*8)
            const char* bn = sB + (ks * 8 + tig) * BPITCH + (wn + g) * 4;
#pragma unroll
            for (int ns = 0; ns < 8; ns++) {
                uint32_t b0 = f2tf32(*(const float*)(bn + ns * 32));
                uint32_t b1 = f2tf32(*(const float*)(bn + 4 * BPITCH + ns * 32));
#pragma unroll
                for (int ms = 0; ms < 2; ms++)
                    mma16888(acc[ms][ns], a[ms], b0, b1);
            }
        }
        if (kt + 1 < NKT) cp_wait0();
        __syncthreads();
    }

    // Epilogue: +bias, f32 pair stores
#pragma unroll
    for (int ns = 0; ns < 8; ns++) {
        const int n = n0 + wn + ns * 8 + 2 * tig;
        float2 bb = *(const float2*)(bias + n);
#pragma unroll
        for (int ms = 0; ms < 2; ms++) {
            const int m = m0 + wm + ms * 16 + g;
            float2 o0, o1;
            o0.x = acc[ms][ns][0] + bb.x;
            o0.y = acc[ms][ns][1] + bb.y;
            o1.x = acc[ms][ns][2] + bb.x;
            o1.y = acc[ms][ns][3] + bb.y;
            *(float2*)(C + (size_t)m * U_DIM + n) = o0;
            *(float2*)(C + (size_t)(m + 8) * U_DIM + n) = o1;
        }
    }
}

// ---------------------------------------------------------------------------
__global__ void indrnn_gemm_naive(
    const float* __restrict__ A, const float* __restrict__ Bw,
    const float* __restrict__ bias, float* __restrict__ Cc,
    int M, int N, int K)
{
    int idx = blockIdx.x * blockDim.x + threadIdx.x;
    if (idx >= M * N) return;
    int m = idx / N, n = idx % N;
    float s = bias[n];
    for (int k = 0; k < K; k++) s = fmaf(A[(size_t)m * K + k], Bw[(size_t)k * N + n], s);
    Cc[idx] = s;
}

// ---------------------------------------------------------------------------
// Scan: one thread per (b,u) chain; depth-32 software pipeline — loads for
// batch i+1 are in flight while batch i is processed/stored.
// ---------------------------------------------------------------------------
__global__ __launch_bounds__(128) void indrnn_scan(
    float* __restrict__ out, const float* __restrict__ h0,
    const float* __restrict__ u, int B, int T, int U)
{
    int idx = blockIdx.x * blockDim.x + threadIdx.x;
    if (idx >= B * U) return;
    int b = idx / U;
    int j = idx - b * U;

    float uc = fminf(fmaxf(u[j], 0.0f), 1.0f);
    float h = h0[idx];
    const size_t st = (size_t)U;
    float* p = out + (size_t)b * T * U + j;

    if ((T & 31) == 0 && T >= 64) {
        float cur[32], nxt[32];
#pragma unroll
        for (int i = 0; i < 32; i++) cur[i] = __ldcg(p + i * st);
        float* pw = p;
        p += 32 * st;

        const int NB = T / 32;
        for (int bI = 1; bI < NB; bI++) {
#pragma unroll
            for (int i = 0; i < 32; i++) nxt[i] = __ldcg(p + i * st);
#pragma unroll
            for (int i = 0; i < 32; i++) {
                h = fmaxf(fmaf(h, uc, cur[i]), 0.0f);
                pw[i * st] = h;
            }
#pragma unroll
            for (int i = 0; i < 32; i++) cur[i] = nxt[i];
            pw = p;
            p += 32 * st;
        }
#pragma unroll
        for (int i = 0; i < 32; i++) {
            h = fmaxf(fmaf(h, uc, cur[i]), 0.0f);
            pw[i * st] = h;
        }
    } else {
        for (int t = 0; t < T; t++) {
            float v = __ldcg(p);
            h = fmaxf(fmaf(h, uc, v), 0.0f);
            *p = h;
            p += st;
        }
    }
}

// ---------------------------------------------------------------------------
extern "C" void kernel_launch(void* const* d_in, const int* in_sizes, int n_in,
                              void* d_out, int out_size)
{
    const float* x  = (const float*)d_in[0];
    const float* h0 = (const float*)d_in[1];
    const float* W  = (const float*)d_in[2];
    const float* u  = (const float*)d_in[3];
    const float* bb = (const float*)d_in[4];
    float* out = (float*)d_out;

    const int U = in_sizes[3];
    const int B = in_sizes[1] / U;
    const int D = in_sizes[2] / U;
    const int T = in_sizes[0] / (B * D);

    const int M = B * T;
    const int N = U;
    const int K = D;

    if (M == M_DIM && N == U_DIM && K == K_DIM) {
        cudaFuncSetAttribute(indrnn_gemm_tf32,
                             cudaFuncAttributeMaxDynamicSharedMemorySize, GEMM_SMEM);
        indrnn_gemm_tf32<<<dim3(N / 128, M / 128), 256, GEMM_SMEM>>>(x, W, bb, out);
    } else {
        int total = M * N;
        indrnn_gemm_naive<<<(total + 255) / 256, 256>>>(x, W, bb, out, M, N, K);
    }

    int chains = B * U;
    indrnn_scan<<<(chains + 127) / 128, 128>>>(out, h0, u, B, T, U);
}